// round 10
// baseline (speedup 1.0000x reference)
#include <cuda_runtime.h>
#include <cstdint>

#define N_TOKENS   262144
#define N_EXPERTS  256
#define TOP_K      8

#define LOGITS_ELEMS   ((size_t)N_TOKENS * N_EXPERTS)   // 67108864
#define TOPK_ELEMS     ((size_t)N_TOKENS * TOP_K)       // 2097152

#define BLOCKS   888           // 148 SMs * 6 blocks -> single clean wave
#define THREADS  256
#define WARPS_PER_BLOCK (THREADS / 32)
#define MAX_SURV 16

// float -> order-preserving uint key (finite floats)
__device__ __forceinline__ unsigned f2key(float f) {
    unsigned u = __float_as_uint(f);
    return u ^ (0x80000000u | (unsigned)((int)u >> 31));
}
__device__ __forceinline__ float key2f(unsigned k) {
    unsigned u = (k & 0x80000000u) ? (k ^ 0x80000000u) : ~k;
    return __uint_as_float(u);
}

__global__ void zero_hist_kernel(float* __restrict__ hist_out) {
    hist_out[threadIdx.x] = 0.0f;
}

__global__ void __launch_bounds__(THREADS, 6)
moe_router_kernel(const float* __restrict__ logits, float* __restrict__ out) {
    __shared__ int   s_hist[N_EXPERTS];
    __shared__ uint2 s_surv[WARPS_PER_BLOCK][MAX_SURV];

    const int tid  = threadIdx.x;
    const int lane = tid & 31;
    const int wip  = tid >> 5;
    const int warp_global = blockIdx.x * WARPS_PER_BLOCK + wip;
    const int n_warps     = BLOCKS * WARPS_PER_BLOCK;

    s_hist[tid] = 0;
    __syncthreads();

    float* __restrict__ outW = out + LOGITS_ELEMS;
    float* __restrict__ outI = outW + TOPK_ELEMS;
    uint2* buf = s_surv[wip];

    for (int tok = warp_global; tok < N_TOKENS; tok += n_warps) {
        const float4* row = (const float4*)(logits + (size_t)tok * N_EXPERTS);
        // INDEX-ORDERED mapping (R6, measured best): lane L owns contiguous
        // [8L, 8L+8). (lane asc, slot asc) == global idx asc, so survivor
        // compaction order == idx order -> 32-bit rank keys + free tie-break.
        float4 a = __ldcs(&row[2 * lane]);
        float4 b = __ldcs(&row[2 * lane + 1]);

        float4* orow = (float4*)(out + (size_t)tok * N_EXPERTS);
        __stcs(&orow[2 * lane],     a);   // streaming pass-through copy
        __stcs(&orow[2 * lane + 1], b);

        float f0=a.x, f1=a.y, f2=a.z, f3=a.w, f4=b.x, f5=b.y, f6=b.z, f7=b.w;
        const unsigned ibase = 8u * lane;

        // per-lane max (7 FMNMX)
        float m = fmaxf(fmaxf(fmaxf(f0,f1), fmaxf(f2,f3)),
                        fmaxf(fmaxf(f4,f5), fmaxf(f6,f7)));

        // T0 = ~8th-largest of the 32 lane maxes = lower bound on global 8th.
        unsigned u = f2key(m);
        unsigned g0 = 0, g = 0;
        #pragma unroll
        for (int r = 0; r < TOP_K; r++) {
            g = __reduce_max_sync(0xffffffffu, u);
            if (r == 0) g0 = g;          // global max key
            u = (u == g) ? 0u : u;
        }
        float T0f = key2f(g);

        // survivor predicates (v >= T0f)
        bool p0=f0>=T0f, p1=f1>=T0f, p2=f2>=T0f, p3=f3>=T0f;
        bool p4=f4>=T0f, p5=f5>=T0f, p6=f6>=T0f, p7=f7>=T0f;
        int cnt = (int)p0+(int)p1+(int)p2+(int)p3+(int)p4+(int)p5+(int)p6+(int)p7;

        // inclusive prefix scan over lanes (idx order)
        int pfx = cnt;
        #pragma unroll
        for (int d = 1; d < 32; d <<= 1) {
            int t = __shfl_up_sync(0xffffffffu, pfx, d);
            if (lane >= d) pfx += t;
        }
        int total = __shfl_sync(0xffffffffu, pfx, 31);
        int base  = pfx - cnt;

        if (total == TOP_K) {
            // ---- express path (~half the tokens): survivors ARE the top-8 ----
            int c = base;
            if (p0) buf[c++] = make_uint2(__float_as_uint(f0), ibase + 0u);
            if (p1) buf[c++] = make_uint2(__float_as_uint(f1), ibase + 1u);
            if (p2) buf[c++] = make_uint2(__float_as_uint(f2), ibase + 2u);
            if (p3) buf[c++] = make_uint2(__float_as_uint(f3), ibase + 3u);
            if (p4) buf[c++] = make_uint2(__float_as_uint(f4), ibase + 4u);
            if (p5) buf[c++] = make_uint2(__float_as_uint(f5), ibase + 5u);
            if (p6) buf[c++] = make_uint2(__float_as_uint(f6), ibase + 6u);
            if (p7) buf[c++] = make_uint2(__float_as_uint(f7), ibase + 7u);
            __syncwarp();

            uint2 sv2 = buf[lane & 7];           // buf order == idx order
            unsigned kk = sv2.x ^ (0x80000000u | (unsigned)((int)sv2.x >> 31));
            unsigned sidx = sv2.y;
            // rank among 8; ties -> lower lane (= lower idx) first
            int rank = 0;
            #pragma unroll
            for (int d = 1; d < 8; d++) {
                unsigned ok = __shfl_xor_sync(0xffffffffu, kk, d, 8);
                rank += (ok > kk) || ((ok == kk) && ((lane ^ d) < lane));
            }

            float vmax = key2f(g0);
            float ex = __expf(__uint_as_float(sv2.x) - vmax);
            float s = ex;
            s += __shfl_xor_sync(0xffffffffu, s, 1, 8);
            s += __shfl_xor_sync(0xffffffffu, s, 2, 8);
            s += __shfl_xor_sync(0xffffffffu, s, 4, 8);

            if (lane < TOP_K) {
                outW[(size_t)tok * TOP_K + rank] = __fdividef(ex, s);
                outI[(size_t)tok * TOP_K + rank] = (float)sidx;
                atomicAdd(&s_hist[sidx], 1);
            }
            __syncwarp();
        } else if (total <= MAX_SURV) {          // 8 < total <= 16
            // ---- general fast path ----
            int c = base;
            if (p0) buf[c++] = make_uint2(__float_as_uint(f0), ibase + 0u);
            if (p1) buf[c++] = make_uint2(__float_as_uint(f1), ibase + 1u);
            if (p2) buf[c++] = make_uint2(__float_as_uint(f2), ibase + 2u);
            if (p3) buf[c++] = make_uint2(__float_as_uint(f3), ibase + 3u);
            if (p4) buf[c++] = make_uint2(__float_as_uint(f4), ibase + 4u);
            if (p5) buf[c++] = make_uint2(__float_as_uint(f5), ibase + 5u);
            if (p6) buf[c++] = make_uint2(__float_as_uint(f6), ibase + 6u);
            if (p7) buf[c++] = make_uint2(__float_as_uint(f7), ibase + 7u);
            __syncwarp();

            uint2 sv2  = buf[lane & (MAX_SURV - 1)];
            bool valid = lane < total;
            unsigned kraw = sv2.x ^ (0x80000000u | (unsigned)((int)sv2.x >> 31));
            unsigned kk   = valid ? kraw : 0u;   // invalid lanes rank last
            unsigned sidx = sv2.y;
            int rank = 0;
            #pragma unroll
            for (int d = 1; d < MAX_SURV; d++) {
                unsigned ok = __shfl_xor_sync(0xffffffffu, kk, d, MAX_SURV);
                rank += (ok > kk) || ((ok == kk) && ((lane ^ d) < lane));
            }

            bool win8 = valid && (rank < TOP_K);
            float vmax = key2f(g0);
            float ex = win8 ? __expf(__uint_as_float(sv2.x) - vmax) : 0.0f;
            float s = ex;
            #pragma unroll
            for (int d = 1; d < MAX_SURV; d <<= 1)
                s += __shfl_xor_sync(0xffffffffu, s, d, MAX_SURV);

            if (win8) {
                outW[(size_t)tok * TOP_K + rank] = __fdividef(ex, s);
                outI[(size_t)tok * TOP_K + rank] = (float)sidx;
                atomicAdd(&s_hist[sidx], 1);
            }
            __syncwarp();
        } else {
            // ---- rare fallback: exact 8-round selection (R5-proven; valid
            // because lane order == idx order under this mapping) ----
            unsigned k[8];
            k[0]=f2key(f0); k[1]=f2key(f1); k[2]=f2key(f2); k[3]=f2key(f3);
            k[4]=f2key(f4); k[5]=f2key(f5); k[6]=f2key(f6); k[7]=f2key(f7);

            unsigned lmax = 0; int lslot = 0;
            #pragma unroll
            for (int j = 0; j < 8; j++) { if (k[j] > lmax) { lmax = k[j]; lslot = j; } }

            unsigned mykey = 0; int myidx = 0;
            #pragma unroll
            for (int r = 0; r < TOP_K; r++) {
                unsigned gg  = __reduce_max_sync(0xffffffffu, lmax);
                unsigned bal = __ballot_sync(0xffffffffu, lmax == gg);
                int win   = __ffs(bal) - 1;                  // lowest lane = lowest idx
                int wslot = __shfl_sync(0xffffffffu, lslot, win);
                if (lane == r) { mykey = gg; myidx = win * 8 + wslot; }
                if (lane == win) {
                    k[lslot] = 0u;
                    lmax = 0; lslot = 0;
                    #pragma unroll
                    for (int j = 0; j < 8; j++) { if (k[j] > lmax) { lmax = k[j]; lslot = j; } }
                }
            }

            float vmax = key2f(__shfl_sync(0xffffffffu, mykey, 0));
            float myval = (lane < TOP_K) ? key2f(mykey) : vmax;  // lanes>=8 unused
            float e = __expf(myval - vmax);
            float s = e;
            s += __shfl_xor_sync(0xffffffffu, s, 1);
            s += __shfl_xor_sync(0xffffffffu, s, 2);
            s += __shfl_xor_sync(0xffffffffu, s, 4);   // sums within 8-lane groups

            if (lane < TOP_K) {
                outW[(size_t)tok * TOP_K + lane] = __fdividef(e, s);
                outI[(size_t)tok * TOP_K + lane] = (float)myidx;
                atomicAdd(&s_hist[myidx], 1);
            }
        }
    }

    __syncthreads();
    float* __restrict__ outH = out + LOGITS_ELEMS + 2 * TOPK_ELEMS;
    int c = s_hist[tid];
    if (c > 0) atomicAdd(&outH[tid], (float)c);
}

extern "C" void kernel_launch(void* const* d_in, const int* in_sizes, int n_in,
                              void* d_out, int out_size) {
    const float* logits = (const float*)d_in[0];
    float* out = (float*)d_out;

    float* hist_region = out + LOGITS_ELEMS + 2 * TOPK_ELEMS;
    zero_hist_kernel<<<1, N_EXPERTS>>>(hist_region);
    moe_router_kernel<<<BLOCKS, THREADS>>>(logits, out);
}